// round 8
// baseline (speedup 1.0000x reference)
#include <cuda_runtime.h>

// PDHG persistent kernel: P=2, C=1, NX=128, NY=128, NT=8, T iterations.
// One thread per (p,x,y) column, all 8 t-values in registers.
// CTA tile = 32 (x) by 8 (y). Grid: 2 planes * 4 * 16 = 128 CTAs (all co-resident
// on 148+ SMs -> spin-wait neighbor sync is deadlock-free).
// Cross-CTA halos through small L2 buffers with acquire/release flag counters.
//
// FROZEN pending first successful measurement (8 broker timeouts so far).
//
// Race-freedom of single-buffered halos (two-hop argument):
//   A CTA overwrites halo version v with v+1 only after passing a flag wait that
//   its consumer publishes strictly after reading version v; wait and overwrite
//   are executed by the same thread. Verified for all four buffers
//   (xbarL, xbarT, qxR, qyB) in both phases.
//
// Memory model: weak .cg halo stores -> __threadfence() (gpu scope) ->
// __syncthreads() -> tid0 st.release.gpu flag. Consumer: ld.acquire.gpu flag
// -> ldcg halo. Release cumulativity carries the fenced stores.

#define NXD 128
#define NYD 128
#define NTD 8
#define TX  32
#define TY  8
#define CXN 4     // 128/32 tiles in x
#define CYN 16    // 128/8  tiles in y
#define NP  2     // planes (P dim)

// halo buffers (accessed with .cg so they stay coherent through L2)
__device__ float4 g_xbarL[NP][CYN][CXN][TY][2];  // x=0  column of each CTA (for left neighbor)
__device__ float4 g_xbarT[NP][CYN][CXN][TX][2];  // y=0  row    of each CTA (for top  neighbor)
__device__ float4 g_qxR [NP][CYN][CXN][TY][2];   // x=31 column of qx       (for right neighbor)
__device__ float4 g_qyB [NP][CYN][CXN][TX][2];   // y=7  row    of qy       (for bottom neighbor)
__device__ int    g_xflag[NP][CYN][CXN];         // flag v+1 <=> xbar version v published
__device__ int    g_qflag[NP][CYN][CXN];         // flag v   <=> q    version v published

__global__ void pdhg_zero_flags()
{
    int i = threadIdx.x;           // exactly NP*CYN*CXN = 128 threads launched
    ((int*)g_xflag)[i] = 0;
    ((int*)g_qflag)[i] = 0;
}

__device__ __forceinline__ int ld_acq(const int* a)
{
    int v;
    asm volatile("ld.acquire.gpu.global.b32 %0, [%1];" : "=r"(v) : "l"(a) : "memory");
    return v;
}
__device__ __forceinline__ void st_rel(int* a, int v)
{
    asm volatile("st.release.gpu.global.b32 [%0], %1;" :: "l"(a), "r"(v) : "memory");
}
// Spin until *a >= v. First poll is the fast path; back off with nanosleep
// afterwards to keep L2 traffic off the neighbor's release store.
__device__ __forceinline__ void wait_flag(const int* a, int v)
{
    if (ld_acq(a) >= v) return;
    while (ld_acq(a) < v) { __nanosleep(32); }
}
// Corner-thread variant: wait until BOTH flags reach v, polling concurrently
// (max of the two latencies instead of their sum).
__device__ __forceinline__ void wait_flag2(const int* a, const int* b, int v)
{
    bool da = (ld_acq(a) >= v);
    bool db = (ld_acq(b) >= v);
    while (!(da && db)) {
        __nanosleep(32);
        if (!da) da = (ld_acq(a) >= v);
        if (!db) db = (ld_acq(b) >= v);
    }
}

__global__ void __launch_bounds__(256, 1)
pdhg_kernel(const float* __restrict__ x_in, const float* __restrict__ lam_in,
            const float* __restrict__ tau_p, const float* __restrict__ sigma_p,
            const float* __restrict__ theta_p, const int* __restrict__ T_p,
            float* __restrict__ out)
{
    __shared__ float4 s_xbar[2][TY][TX];   // xbar tile (for y+1 access)
    __shared__ float4 s_qy[2][TY][TX];     // qy tile   (for y-1 access)

    const int tid = threadIdx.x;
    const int lx  = tid & 31;          // warp = one x-row of 32
    const int ly  = tid >> 5;
    const int blk = blockIdx.x;
    const int pl  = blk >> 6;          // plane
    const int cc  = blk & 63;
    const int cx  = cc & 3;
    const int cy  = cc >> 2;
    const int gx  = cx * TX + lx;
    const int gy  = cy * TY + ly;
    const int cxR = (cx + 1) & 3,  cxL = (cx + 3) & 3;
    const int cyB = (cy + 1) & 15, cyT = (cy + 15) & 15;

    const float Li   = 1.0f / sqrtf(13.0f);
    const float sig  = Li / (1.0f + expf(-__ldg(sigma_p)));
    const float tauL = Li / (1.0f + expf(-__ldg(tau_p)));
    const float th   = 1.0f / (1.0f + expf(-__ldg(theta_p)));
    const float i1s  = 1.0f / (1.0f + sig);
    const int   T    = T_p ? __ldg(T_p) : 128;

    const int base = ((pl * NXD + gx) * NYD + gy) * NTD;

    float xn[NTD], lam[NTD], nlam[NTD], x0[NTD], xbar[NTD], p[NTD];
    float qx[NTD], qy[NTD], qt[NTD];
    {
        float4 a = *(const float4*)(x_in + base);
        float4 b = *(const float4*)(x_in + base + 4);
        xn[0]=a.x; xn[1]=a.y; xn[2]=a.z; xn[3]=a.w;
        xn[4]=b.x; xn[5]=b.y; xn[6]=b.z; xn[7]=b.w;
        float4 c = *(const float4*)(lam_in + base);
        float4 d = *(const float4*)(lam_in + base + 4);
        lam[0]=c.x; lam[1]=c.y; lam[2]=c.z; lam[3]=c.w;
        lam[4]=d.x; lam[5]=d.y; lam[6]=d.z; lam[7]=d.w;
    }
#pragma unroll
    for (int t = 0; t < NTD; t++) {
        x0[t] = xn[t]; xbar[t] = xn[t]; p[t] = xn[t];
        qx[t] = 0.f; qy[t] = 0.f; qt[t] = 0.f;
        nlam[t] = -lam[t];                    // hoisted: kills per-iter FNEG
    }

    // ---- publish initial xbar (version 0) ----
    s_xbar[0][ly][lx] = make_float4(xbar[0], xbar[1], xbar[2], xbar[3]);
    s_xbar[1][ly][lx] = make_float4(xbar[4], xbar[5], xbar[6], xbar[7]);
    if (lx == 0) {
        __stcg(&g_xbarL[pl][cy][cx][ly][0], make_float4(xbar[0], xbar[1], xbar[2], xbar[3]));
        __stcg(&g_xbarL[pl][cy][cx][ly][1], make_float4(xbar[4], xbar[5], xbar[6], xbar[7]));
    }
    if (ly == 0) {
        __stcg(&g_xbarT[pl][cy][cx][lx][0], make_float4(xbar[0], xbar[1], xbar[2], xbar[3]));
        __stcg(&g_xbarT[pl][cy][cx][lx][1], make_float4(xbar[4], xbar[5], xbar[6], xbar[7]));
    }
    if (lx == 0 || ly == 0) __threadfence();
    __syncthreads();
    if (tid == 0) st_rel(&g_xflag[pl][cy][cx], 1);

    for (int it = 1; it <= T; ++it) {
        // ================= Phase A : dual (q) update =================
        // needs xbar version it-1 at (x+1) and (y+1)
        float hxr[NTD], hxb[NTD];
        {
            const bool eR = (lx == 31), eB = (ly == TY - 1);
            if (eR && eB)      wait_flag2(&g_xflag[pl][cy][cxR], &g_xflag[pl][cyB][cx], it);
            else if (eR)       wait_flag(&g_xflag[pl][cy][cxR], it);
            else if (eB)       wait_flag(&g_xflag[pl][cyB][cx], it);
            if (eR) {
                float4 a = __ldcg(&g_xbarL[pl][cy][cxR][ly][0]);
                float4 b = __ldcg(&g_xbarL[pl][cy][cxR][ly][1]);
                hxr[0]=a.x; hxr[1]=a.y; hxr[2]=a.z; hxr[3]=a.w;
                hxr[4]=b.x; hxr[5]=b.y; hxr[6]=b.z; hxr[7]=b.w;
            }
            if (eB) {
                float4 a = __ldcg(&g_xbarT[pl][cyB][cx][lx][0]);
                float4 b = __ldcg(&g_xbarT[pl][cyB][cx][lx][1]);
                hxb[0]=a.x; hxb[1]=a.y; hxb[2]=a.z; hxb[3]=a.w;
                hxb[4]=b.x; hxb[5]=b.y; hxb[6]=b.z; hxb[7]=b.w;
            }
        }
        float xp1[NTD];
        if (ly < TY - 1) {
            float4 a = s_xbar[0][ly + 1][lx];
            float4 b = s_xbar[1][ly + 1][lx];
            xp1[0]=a.x; xp1[1]=a.y; xp1[2]=a.z; xp1[3]=a.w;
            xp1[4]=b.x; xp1[5]=b.y; xp1[6]=b.z; xp1[7]=b.w;
        } else {
#pragma unroll
            for (int t = 0; t < NTD; t++) xp1[t] = hxb[t];
        }
#pragma unroll
        for (int t = 0; t < NTD; t++) {
            float xr = __shfl_down_sync(0xffffffffu, xbar[t], 1);
            if (lx == 31) xr = hxr[t];
            float a = qx[t] + sig * (xr             - xbar[t]);
            float b = qy[t] + sig * (xp1[t]         - xbar[t]);
            float c = qt[t] + sig * (xbar[(t+1)&7]  - xbar[t]);
            // q*lam/max(lam,|q|) == clamp(q, -lam, lam)
            qx[t] = fminf(fmaxf(a, nlam[t]), lam[t]);
            qy[t] = fminf(fmaxf(b, nlam[t]), lam[t]);
            qt[t] = fminf(fmaxf(c, nlam[t]), lam[t]);
        }
        s_qy[0][ly][lx] = make_float4(qy[0], qy[1], qy[2], qy[3]);
        s_qy[1][ly][lx] = make_float4(qy[4], qy[5], qy[6], qy[7]);
        if (lx == 31) {
            __stcg(&g_qxR[pl][cy][cx][ly][0], make_float4(qx[0], qx[1], qx[2], qx[3]));
            __stcg(&g_qxR[pl][cy][cx][ly][1], make_float4(qx[4], qx[5], qx[6], qx[7]));
        }
        if (ly == TY - 1) {
            __stcg(&g_qyB[pl][cy][cx][lx][0], make_float4(qy[0], qy[1], qy[2], qy[3]));
            __stcg(&g_qyB[pl][cy][cx][lx][1], make_float4(qy[4], qy[5], qy[6], qy[7]));
        }
        if (lx == 31 || ly == TY - 1) __threadfence();
        __syncthreads();
        if (tid == 0) st_rel(&g_qflag[pl][cy][cx], it);

        // ================= Phase B : primal update =================
        // needs q version it at (x-1) and (y-1)
        float hqx[NTD], hqy[NTD];
        {
            const bool eL = (lx == 0), eT = (ly == 0);
            if (eL && eT)      wait_flag2(&g_qflag[pl][cy][cxL], &g_qflag[pl][cyT][cx], it);
            else if (eL)       wait_flag(&g_qflag[pl][cy][cxL], it);
            else if (eT)       wait_flag(&g_qflag[pl][cyT][cx], it);
            if (eL) {
                float4 a = __ldcg(&g_qxR[pl][cy][cxL][ly][0]);
                float4 b = __ldcg(&g_qxR[pl][cy][cxL][ly][1]);
                hqx[0]=a.x; hqx[1]=a.y; hqx[2]=a.z; hqx[3]=a.w;
                hqx[4]=b.x; hqx[5]=b.y; hqx[6]=b.z; hqx[7]=b.w;
            }
            if (eT) {
                float4 a = __ldcg(&g_qyB[pl][cyT][cx][lx][0]);
                float4 b = __ldcg(&g_qyB[pl][cyT][cx][lx][1]);
                hqy[0]=a.x; hqy[1]=a.y; hqy[2]=a.z; hqy[3]=a.w;
                hqy[4]=b.x; hqy[5]=b.y; hqy[6]=b.z; hqy[7]=b.w;
            }
        }
        float qym[NTD];
        if (ly > 0) {
            float4 a = s_qy[0][ly - 1][lx];
            float4 b = s_qy[1][ly - 1][lx];
            qym[0]=a.x; qym[1]=a.y; qym[2]=a.z; qym[3]=a.w;
            qym[4]=b.x; qym[5]=b.y; qym[6]=b.z; qym[7]=b.w;
        } else {
#pragma unroll
            for (int t = 0; t < NTD; t++) qym[t] = hqy[t];
        }
#pragma unroll
        for (int t = 0; t < NTD; t++) {
            float qxm = __shfl_up_sync(0xffffffffu, qx[t], 1);
            if (lx == 0) qxm = hqx[t];
            float div = (qxm - qx[t]) + (qym[t] - qy[t]) + (qt[(t+7)&7] - qt[t]);
            float np  = (p[t] + sig * (xbar[t] - xn[t])) * i1s;
            p[t] = np;
            float x1 = x0[t] - tauL * np - tauL * div;
            xbar[t]  = x1 + th * (x1 - x0[t]);
            x0[t]    = x1;
        }
        s_xbar[0][ly][lx] = make_float4(xbar[0], xbar[1], xbar[2], xbar[3]);
        s_xbar[1][ly][lx] = make_float4(xbar[4], xbar[5], xbar[6], xbar[7]);
        if (lx == 0) {
            __stcg(&g_xbarL[pl][cy][cx][ly][0], make_float4(xbar[0], xbar[1], xbar[2], xbar[3]));
            __stcg(&g_xbarL[pl][cy][cx][ly][1], make_float4(xbar[4], xbar[5], xbar[6], xbar[7]));
        }
        if (ly == 0) {
            __stcg(&g_xbarT[pl][cy][cx][lx][0], make_float4(xbar[0], xbar[1], xbar[2], xbar[3]));
            __stcg(&g_xbarT[pl][cy][cx][lx][1], make_float4(xbar[4], xbar[5], xbar[6], xbar[7]));
        }
        if (lx == 0 || ly == 0) __threadfence();
        __syncthreads();
        if (tid == 0) st_rel(&g_xflag[pl][cy][cx], it + 1);
    }

    *(float4*)(out + base)     = make_float4(x0[0], x0[1], x0[2], x0[3]);
    *(float4*)(out + base + 4) = make_float4(x0[4], x0[5], x0[6], x0[7]);
}

extern "C" void kernel_launch(void* const* d_in, const int* in_sizes, int n_in,
                              void* d_out, int out_size)
{
    const float* x    = (const float*)d_in[0];
    const float* lam  = (const float*)d_in[1];
    const float* tau  = (const float*)d_in[2];
    const float* sigm = (const float*)d_in[3];
    const float* thet = (const float*)d_in[4];
    const int*   T    = (n_in >= 6) ? (const int*)d_in[5] : nullptr;
    float* o = (float*)d_out;

    pdhg_zero_flags<<<1, NP * CYN * CXN>>>();          // reset flag counters each launch
    pdhg_kernel<<<NP * CYN * CXN, 256>>>(x, lam, tau, sigm, thet, T, o);
}